// round 1
// baseline (speedup 1.0000x reference)
#include <cuda_runtime.h>
#include <math.h>

// Problem constants (fixed shapes: 512 x 16 x 128)
#define NTOT 8192     // N = B*C
#define DDIM 128      // feature dim
#define BM 64         // rows per CTA
#define BN 128        // cols per tile
#define NRT (NTOT/BM) // 128 row tiles (= grid)
#define NJT (NTOT/BN) // 64 col tiles
#define TM 4
#define TN 8
#define NTHREADS 256
#define INVT 100.0f   // 1/temperature
#define BS_STRIDE (BN + 1)  // 129, pad to reduce smem bank conflicts
#define EXP_SKIP 25.0f

// Scratch (device globals — no dynamic allocation allowed)
__device__ float g_row_lse[NTOT];
__device__ float g_diag[NTOT];
__device__ float g_cpm[NRT * NTOT];   // per-row-stripe column max partials (4MB)
__device__ float g_cps[NRT * NTOT];   // per-row-stripe column sumexp partials (4MB)
__device__ float g_term[NTOT];

__device__ __forceinline__ void lse_merge(float& M, float& S, float m2, float s2) {
    if (m2 > M) {
        S = S * __expf(M - m2) + s2;   // expf(-inf)=0, 0*0=0: safe for M=-inf
        M = m2;
    } else if (m2 != -INFINITY) {
        S += s2 * __expf(m2 - M);
    }
}

// Smem: As[BM*DDIM] + Bs[DDIM*BS_STRIDE] + red[BN*16] (float2)
#define SMEM_FLOATS (BM*DDIM + DDIM*BS_STRIDE)
#define SMEM_BYTES  (SMEM_FLOATS*4 + BN*16*8)

__global__ void __launch_bounds__(NTHREADS, 1)
cont_main(const float* __restrict__ ts, const float* __restrict__ nt) {
    extern __shared__ float smem[];
    float*  As  = smem;                       // [row][k], row-major
    float*  Bs  = smem + BM * DDIM;           // [k][j],   k-major, padded
    float2* red = (float2*)(smem + SMEM_FLOATS);

    const int t  = threadIdx.x;
    const int tx = t & 15;
    const int ty = t >> 4;
    const int rt = blockIdx.x;
    const int r0 = rt * BM;
    const int mask_jt = r0 >> 7;  // the one j-tile containing this CTA's diag blocks

    // Load A tile (64x128 = contiguous 8192 floats), stays resident all kernel
    {
        const float4* g = (const float4*)(ts + (size_t)r0 * DDIM);
        float4* s4 = (float4*)As;
        #pragma unroll
        for (int it = 0; it < (BM*DDIM/4)/NTHREADS; it++)
            s4[t + it*NTHREADS] = g[t + it*NTHREADS];
    }

    // Online row LSE state (persists across all j-tiles)
    float m[TM], s[TM];
    #pragma unroll
    for (int r = 0; r < TM; r++) { m[r] = -INFINITY; s[r] = 0.0f; }

    for (int jt = 0; jt < NJT; jt++) {
        // Load B tile transposed -> Bs[k][j]
        {
            const float4* g = (const float4*)(nt + (size_t)jt * BN * DDIM);
            #pragma unroll
            for (int it = 0; it < (BN*DDIM/4)/NTHREADS; it++) {
                int e4 = t + it*NTHREADS;
                float4 v = g[e4];
                int j = e4 >> 5;          // 32 float4 per source row
                int k = (e4 & 31) * 4;
                Bs[(k+0)*BS_STRIDE + j] = v.x;
                Bs[(k+1)*BS_STRIDE + j] = v.y;
                Bs[(k+2)*BS_STRIDE + j] = v.z;
                Bs[(k+3)*BS_STRIDE + j] = v.w;
            }
        }
        __syncthreads();  // Bs ready (also: prior tile's red-merge done, As ready on it 0)

        // 64x128 tile GEMM, 4x8 register tile per thread
        float acc[TM][TN];
        #pragma unroll
        for (int r = 0; r < TM; r++)
            #pragma unroll
            for (int c = 0; c < TN; c++) acc[r][c] = 0.0f;

        #pragma unroll 4
        for (int k = 0; k < DDIM; k++) {
            float a[TM], b[TN];
            #pragma unroll
            for (int r = 0; r < TM; r++) a[r] = As[(ty + r*16)*DDIM + k];
            #pragma unroll
            for (int c = 0; c < TN; c++) b[c] = Bs[k*BS_STRIDE + tx + c*16];
            #pragma unroll
            for (int r = 0; r < TM; r++)
                #pragma unroll
                for (int c = 0; c < TN; c++)
                    acc[r][c] = fmaf(a[r], b[c], acc[r][c]);
        }

        // Epilogue: mask + online row/col LSE
        float cm[TN], cs[TN];
        #pragma unroll
        for (int c = 0; c < TN; c++) { cm[c] = -INFINITY; cs[c] = 0.0f; }

        const bool mt = (jt == mask_jt);
        #pragma unroll
        for (int r = 0; r < TM; r++) {
            const int gi = r0 + ty + r*16;
            #pragma unroll
            for (int c = 0; c < TN; c++) {
                const float v = acc[r][c] * INVT;
                bool valid = true;
                if (mt) {
                    const int gj = jt*BN + tx + c*16;
                    if ((gi >> 4) == (gj >> 4)) {
                        if (gi == gj) g_diag[gi] = v;   // diagonal kept in softmax
                        else          valid = false;    // masked (-1e6 -> exp==0)
                    }
                }
                if (valid) {
                    // row update
                    if (v > m[r]) { s[r] = s[r]*__expf(m[r]-v) + 1.0f; m[r] = v; }
                    else if (v > m[r] - EXP_SKIP) s[r] += __expf(v - m[r]);
                    // col update (per-tile local)
                    if (v > cm[c]) { cs[c] = cs[c]*__expf(cm[c]-v) + 1.0f; cm[c] = v; }
                    else if (v > cm[c] - EXP_SKIP) cs[c] += __expf(v - cm[c]);
                }
            }
        }

        // Column reduce across the 16 ty-threads; each column visited once per CTA
        #pragma unroll
        for (int c = 0; c < TN; c++)
            red[(tx + c*16)*16 + ty] = make_float2(cm[c], cs[c]);
        __syncthreads();
        if (t < BN) {
            float M = -INFINITY, S = 0.0f;
            #pragma unroll
            for (int p = 0; p < 16; p++) {
                float2 pr = red[t*16 + p];
                lse_merge(M, S, pr.x, pr.y);
            }
            g_cpm[(size_t)rt*NTOT + jt*BN + t] = M;
            g_cps[(size_t)rt*NTOT + jt*BN + t] = S;
        }
        // next iteration's post-load __syncthreads orders red reuse / Bs overwrite
    }

    // Finalize row LSE: merge 16 tx partials per row
    __syncthreads();
    #pragma unroll
    for (int r = 0; r < TM; r++)
        red[(ty + r*16)*16 + tx] = make_float2(m[r], s[r]);
    __syncthreads();
    if (t < BM) {
        float M = -INFINITY, S = 0.0f;
        #pragma unroll
        for (int p = 0; p < 16; p++) {
            float2 pr = red[t*16 + p];
            lse_merge(M, S, pr.x, pr.y);
        }
        g_row_lse[r0 + t] = M + __logf(S);
    }
}

// Merge the 128 per-stripe column partials -> col LSE, emit per-index term
__global__ void cont_colmerge() {
    const int j = blockIdx.x * blockDim.x + threadIdx.x;
    float M = -INFINITY, S = 0.0f;
    for (int p = 0; p < NRT; p++)
        lse_merge(M, S, g_cpm[(size_t)p*NTOT + j], g_cps[(size_t)p*NTOT + j]);
    const float col_lse = M + __logf(S);
    g_term[j] = 0.5f * (g_row_lse[j] + col_lse) - g_diag[j];
}

// Final mean reduction -> scalar loss
__global__ void cont_final(float* out) {
    __shared__ float sm[256];
    float acc = 0.0f;
    for (int i = threadIdx.x; i < NTOT; i += 256) acc += g_term[i];
    sm[threadIdx.x] = acc;
    __syncthreads();
    for (int off = 128; off > 0; off >>= 1) {
        if (threadIdx.x < off) sm[threadIdx.x] += sm[threadIdx.x + off];
        __syncthreads();
    }
    if (threadIdx.x == 0) {
        float loss = sm[0] / (float)NTOT;
        if (isnan(loss) || isinf(loss)) loss = 0.0f;
        out[0] = loss;
    }
}

extern "C" void kernel_launch(void* const* d_in, const int* in_sizes, int n_in,
                              void* d_out, int out_size) {
    const float* ts = (const float*)d_in[0];
    const float* nt = (const float*)d_in[1];
    (void)in_sizes; (void)n_in; (void)out_size;

    cudaFuncSetAttribute(cont_main, cudaFuncAttributeMaxDynamicSharedMemorySize, SMEM_BYTES);
    cont_main<<<NRT, NTHREADS, SMEM_BYTES>>>(ts, nt);
    cont_colmerge<<<NTOT/256, 256>>>();
    cont_final<<<1, 256>>>((float*)d_out);
}

// round 4
// speedup vs baseline: 3.3154x; 3.3154x over previous
#include <cuda_runtime.h>
#include <cuda_bf16.h>
#include <cstdint>
#include <math.h>

// Shapes fixed: ts/note (512,16,128) fp32 -> N=8192, D=128
#define NTOT 8192
#define DDIM 128
#define INVT 100.0f

// ---------------- device globals (no dynamic alloc allowed) ----------------
__device__ __align__(16) __nv_bfloat16 g_tsb[NTOT * DDIM];
__device__ __align__(16) __nv_bfloat16 g_ntb[NTOT * DDIM];
__device__ float g_diag[NTOT];
__device__ __align__(16) float2 g_rpart[NTOT][2][8];   // [row][dir][js*4 + nwarp]

// ---------------- helpers ----------------
__device__ __forceinline__ uint32_t smem_u32(const void* p) {
    uint32_t a;
    asm("{ .reg .u64 t; cvta.to.shared.u64 t, %1; cvt.u32.u64 %0, t; }" : "=r"(a) : "l"(p));
    return a;
}
// swizzle for 256B rows: XOR 16B-unit index bits[6:4] with row&7 (bits[10:8])
#define SWZ(off) ((off) ^ (((off) >> 4) & 0x70u))

__device__ __forceinline__ void ldsm_x4(uint32_t* r, uint32_t addr) {
    asm volatile("ldmatrix.sync.aligned.m8n8.x4.shared.b16 {%0,%1,%2,%3}, [%4];"
        : "=r"(r[0]), "=r"(r[1]), "=r"(r[2]), "=r"(r[3]) : "r"(addr));
}
__device__ __forceinline__ void mma_bf16(float* c, const uint32_t* a, const uint32_t* b) {
    asm volatile("mma.sync.aligned.m16n8k16.row.col.f32.bf16.bf16.f32 "
        "{%0,%1,%2,%3}, {%4,%5,%6,%7}, {%8,%9}, {%0,%1,%2,%3};"
        : "+f"(c[0]), "+f"(c[1]), "+f"(c[2]), "+f"(c[3])
        : "r"(a[0]), "r"(a[1]), "r"(a[2]), "r"(a[3]), "r"(b[0]), "r"(b[1]));
}
// copy one 128x128 bf16 tile (32KB) gmem->smem with swizzle; 8x 16B per thread
__device__ __forceinline__ void prefetch_tile(uint32_t sdst, const __nv_bfloat16* src, int tid) {
    const char* s = (const char*)src;
    #pragma unroll
    for (int i = 0; i < 8; i++) {
        uint32_t g = (uint32_t)tid * 8u + i;
        uint32_t off = (g >> 4) * 256u + (g & 15u) * 16u;
        uint32_t dst = sdst + SWZ(off);
        asm volatile("cp.async.cg.shared.global [%0], [%1], 16;" :: "r"(dst), "l"(s + off) : "memory");
    }
}
__device__ __forceinline__ void lse_merge(float& M, float& S, float m2, float s2) {
    if (m2 > M) { S = S * __expf(M - m2) + s2; M = m2; }
    else if (m2 != -INFINITY) S += s2 * __expf(m2 - M);
}

// ============ kernel 1: fp32 -> bf16 row-major ============
__global__ void conv_kernel(const float* __restrict__ ts, const float* __restrict__ nt) {
    int id = blockIdx.x * blockDim.x + threadIdx.x;  // 262144
    int mat = id >> 17;
    int r = id & 131071;
    int row = r >> 4, g = r & 15;                    // 16B granule within row
    const float* src = (mat ? nt : ts) + (size_t)row * DDIM + g * 8;
    float4 v0 = *(const float4*)(src);
    float4 v1 = *(const float4*)(src + 4);
    __nv_bfloat162 b0 = __floats2bfloat162_rn(v0.x, v0.y);
    __nv_bfloat162 b1 = __floats2bfloat162_rn(v0.z, v0.w);
    __nv_bfloat162 b2 = __floats2bfloat162_rn(v1.x, v1.y);
    __nv_bfloat162 b3 = __floats2bfloat162_rn(v1.z, v1.w);
    uint4 pk;
    pk.x = *(uint32_t*)&b0; pk.y = *(uint32_t*)&b1;
    pk.z = *(uint32_t*)&b2; pk.w = *(uint32_t*)&b3;
    uint4* dst = (uint4*)((mat ? g_ntb : g_tsb) + (size_t)row * DDIM) + g;
    *dst = pk;
}

// ============ kernel 2: mma.sync GEMM + fused online row-LSE ============
// grid 256: dir = bx&1, js = (bx>>1)&1, rt = bx>>2
// CTA tile 128(M) x 128(N per j-tile) x 128(K), 32 j-tiles per CTA.
#define DYN_SMEM (96 * 1024 + 1024)

__global__ void __launch_bounds__(256, 2) cont_mma() {
    extern __shared__ __align__(16) char smraw[];
    const uint32_t sb = (smem_u32(smraw) + 1023u) & ~1023u;
    const uint32_t sA = sb, sB0 = sb + 32768u, sB1 = sb + 65536u;

    const int tid = threadIdx.x, lid = tid & 31, wid = tid >> 5;
    const int mwarp = wid >> 2, nwarp = wid & 3;
    const int bx = blockIdx.x;
    const int dir = bx & 1, js = (bx >> 1) & 1, rt = bx >> 2;
    const __nv_bfloat16* Ag = (dir ? g_ntb : g_tsb) + (size_t)rt * 128 * DDIM;
    const __nv_bfloat16* Bg = (dir ? g_tsb : g_ntb) + (size_t)js * 4096 * DDIM;
    const int r0 = rt * 128;
    const int diag_jt = rt - js * 32;   // index of masked tile, if in [0,32)

    // pipeline prologue: G0 = A + B0, G1 = B1
    prefetch_tile(sA, Ag, tid);
    prefetch_tile(sB0, Bg, tid);
    asm volatile("cp.async.commit_group;" ::: "memory");
    prefetch_tile(sB1, Bg + 128 * DDIM, tid);
    asm volatile("cp.async.commit_group;" ::: "memory");

    // per-lane ldmatrix address constants
    const uint32_t X = (uint32_t)(lid & 7) << 4;            // same for A and B rows
    const uint32_t cbhA = ((lid >> 4) & 1) * 16u;
    const uint32_t cbhB = ((lid >> 3) & 1) * 16u;
    uint32_t rowA[4], rowB[2];
    #pragma unroll
    for (int mt = 0; mt < 4; mt++)
        rowA[mt] = (uint32_t)(mwarp * 64 + mt * 16 + (lid & 15)) * 256u;
    #pragma unroll
    for (int np = 0; np < 2; np++)
        rowB[np] = (uint32_t)(nwarp * 32 + np * 16 + (lid & 7) + ((lid >> 4) & 1) * 8) * 256u;

    float m8[8], s8[8];
    #pragma unroll
    for (int i = 0; i < 8; i++) { m8[i] = -INFINITY; s8[i] = 0.0f; }

    for (int jt = 0; jt < 32; jt++) {
        const uint32_t sBuf = (jt & 1) ? sB1 : sB0;
        if (jt < 31) asm volatile("cp.async.wait_group 1;" ::: "memory");
        else         asm volatile("cp.async.wait_group 0;" ::: "memory");
        __syncthreads();

        float acc[4][4][4];
        #pragma unroll
        for (int mt = 0; mt < 4; mt++)
            #pragma unroll
            for (int nt = 0; nt < 4; nt++)
                #pragma unroll
                for (int q = 0; q < 4; q++) acc[mt][nt][q] = 0.0f;

        #pragma unroll
        for (int kt = 0; kt < 8; kt++) {
            const uint32_t kb = (uint32_t)kt * 32u;
            uint32_t bfr[4][2];
            #pragma unroll
            for (int np = 0; np < 2; np++) {
                uint32_t t[4];
                ldsm_x4(t, sBuf + rowB[np] + ((kb + cbhB) ^ X));
                bfr[np * 2][0] = t[0]; bfr[np * 2][1] = t[1];
                bfr[np * 2 + 1][0] = t[2]; bfr[np * 2 + 1][1] = t[3];
            }
            #pragma unroll
            for (int mt = 0; mt < 4; mt++) {
                uint32_t afr[4];
                ldsm_x4(afr, sA + rowA[mt] + ((kb + cbhA) ^ X));
                #pragma unroll
                for (int nt = 0; nt < 4; nt++)
                    mma_bf16(acc[mt][nt], afr, bfr[nt]);
            }
        }

        // ---- epilogue: online row-LSE, exp-skip threshold 25 ----
        if (jt != diag_jt) {
            #pragma unroll
            for (int mt = 0; mt < 4; mt++)
            #pragma unroll
            for (int h = 0; h < 2; h++) {
                const int rs = mt * 2 + h;
                float amax = acc[mt][0][h * 2];
                #pragma unroll
                for (int nt = 0; nt < 4; nt++)
                    #pragma unroll
                    for (int c = 0; c < 2; c++)
                        amax = fmaxf(amax, acc[mt][nt][h * 2 + c]);
                const float vm = amax * INVT;
                if (vm > m8[rs]) { s8[rs] *= __expf(m8[rs] - vm); m8[rs] = vm; }
                const float thr = (m8[rs] - 25.0f) * (1.0f / INVT);
                #pragma unroll
                for (int nt = 0; nt < 4; nt++)
                    #pragma unroll
                    for (int c = 0; c < 2; c++) {
                        const float a = acc[mt][nt][h * 2 + c];
                        if (a > thr) s8[rs] += __expf(fmaf(a, INVT, -m8[rs]));
                    }
            }
        } else {
            // masked tile: per-element block-diagonal mask + diag capture
            #pragma unroll
            for (int mt = 0; mt < 4; mt++)
            #pragma unroll
            for (int h = 0; h < 2; h++) {
                const int rs = mt * 2 + h;
                const int gi = r0 + mwarp * 64 + mt * 16 + (lid >> 2) + h * 8;
                #pragma unroll
                for (int nt = 0; nt < 4; nt++)
                    #pragma unroll
                    for (int c = 0; c < 2; c++) {
                        const int gj = js * 4096 + jt * 128 + nwarp * 32 + nt * 8 + (lid & 3) * 2 + c;
                        const float v = acc[mt][nt][h * 2 + c] * INVT;
                        const bool sameblk = (((gi ^ gj) >> 4) == 0);
                        const bool isdiag = (gi == gj);
                        if (isdiag && dir == 0) g_diag[gi] = v;
                        if (!sameblk || isdiag) {
                            if (v > m8[rs]) { s8[rs] = s8[rs] * __expf(m8[rs] - v) + 1.0f; m8[rs] = v; }
                            else if (v > m8[rs] - 25.0f) s8[rs] += __expf(v - m8[rs]);
                        }
                    }
            }
        }

        __syncthreads();
        if (jt + 2 < 32) {
            prefetch_tile(sBuf, Bg + (size_t)(jt + 2) * 128 * DDIM, tid);
            asm volatile("cp.async.commit_group;" ::: "memory");
        }
    }

    // merge across the 4 lanes sharing a row (l&3 varies cols only), then write
    #pragma unroll
    for (int mt = 0; mt < 4; mt++)
    #pragma unroll
    for (int h = 0; h < 2; h++) {
        const int rs = mt * 2 + h;
        float m = m8[rs], s = s8[rs];
        #pragma unroll
        for (int d = 1; d <= 2; d <<= 1) {
            float om = __shfl_xor_sync(0xFFFFFFFFu, m, d);
            float os = __shfl_xor_sync(0xFFFFFFFFu, s, d);
            lse_merge(m, s, om, os);
        }
        if ((lid & 3) == 0) {
            const int gi = r0 + mwarp * 64 + mt * 16 + (lid >> 2) + h * 8;
            g_rpart[gi][dir][js * 4 + nwarp] = make_float2(m, s);
        }
    }
}

// ============ kernel 3: merge partials -> loss ============
__global__ void cont_fin(float* out) {
    __shared__ float red[256];
    const int tid = threadIdx.x;
    float acc = 0.0f;
    for (int i = tid; i < NTOT; i += 256) {
        float tot = 0.0f;
        #pragma unroll
        for (int d = 0; d < 2; d++) {
            float M = -INFINITY, S = 0.0f;
            #pragma unroll
            for (int k = 0; k < 8; k++) {
                float2 p = g_rpart[i][d][k];
                lse_merge(M, S, p.x, p.y);
            }
            tot += M + __logf(S);
        }
        acc += 0.5f * tot - g_diag[i];
    }
    red[tid] = acc;
    __syncthreads();
    for (int o = 128; o > 0; o >>= 1) {
        if (tid < o) red[tid] += red[tid + o];
        __syncthreads();
    }
    if (tid == 0) {
        float loss = red[0] / (float)NTOT;
        if (isnan(loss) || isinf(loss)) loss = 0.0f;
        out[0] = loss;
    }
}

extern "C" void kernel_launch(void* const* d_in, const int* in_sizes, int n_in,
                              void* d_out, int out_size) {
    const float* ts = (const float*)d_in[0];
    const float* nt = (const float*)d_in[1];
    (void)in_sizes; (void)n_in; (void)out_size;

    conv_kernel<<<1024, 256>>>(ts, nt);
    cudaFuncSetAttribute(cont_mma, cudaFuncAttributeMaxDynamicSharedMemorySize, DYN_SMEM);
    cont_mma<<<256, 256, DYN_SMEM>>>();
    cont_fin<<<1, 256>>>((float*)d_out);
}

// round 5
// speedup vs baseline: 6.4614x; 1.9489x over previous
#include <cuda_runtime.h>
#include <cuda_bf16.h>
#include <cstdint>
#include <math.h>

// Shapes fixed: ts/note (512,16,128) fp32 -> N=8192, D=128
#define NTOT 8192
#define DDIM 128
#define INVT 100.0f

// ---------------- device globals (no dynamic alloc allowed) ----------------
__device__ __align__(16) __nv_bfloat16 g_tsb[NTOT * DDIM];
__device__ __align__(16) __nv_bfloat16 g_ntb[NTOT * DDIM];
__device__ float g_diag[NTOT];
__device__ __align__(16) float2 g_rowp[NTOT][8];     // [row][js*2 + nwarp]
__device__ __align__(16) float2 g_colp[64][NTOT];    // [rt][col]
__device__ float g_bsum[32];

// ---------------- helpers ----------------
__device__ __forceinline__ uint32_t smem_u32(const void* p) {
    uint32_t a;
    asm("{ .reg .u64 t; cvta.to.shared.u64 t, %1; cvt.u32.u64 %0, t; }" : "=r"(a) : "l"(p));
    return a;
}
// swizzle for 256B rows: XOR 16B-unit index bits[6:4] with row&7 (bits[10:8])
#define SWZ(off) ((off) ^ (((off) >> 4) & 0x70u))

__device__ __forceinline__ void ldsm_x4(uint32_t* r, uint32_t addr) {
    asm volatile("ldmatrix.sync.aligned.m8n8.x4.shared.b16 {%0,%1,%2,%3}, [%4];"
        : "=r"(r[0]), "=r"(r[1]), "=r"(r[2]), "=r"(r[3]) : "r"(addr));
}
__device__ __forceinline__ void mma_bf16(float* c, const uint32_t* a, const uint32_t* b) {
    asm volatile("mma.sync.aligned.m16n8k16.row.col.f32.bf16.bf16.f32 "
        "{%0,%1,%2,%3}, {%4,%5,%6,%7}, {%8,%9}, {%0,%1,%2,%3};"
        : "+f"(c[0]), "+f"(c[1]), "+f"(c[2]), "+f"(c[3])
        : "r"(a[0]), "r"(a[1]), "r"(a[2]), "r"(a[3]), "r"(b[0]), "r"(b[1]));
}
// A tile: 32KB (128 rows x 256B), 8 x 16B per thread
__device__ __forceinline__ void pf_a(uint32_t sdst, const __nv_bfloat16* src, int tid) {
    const char* s = (const char*)src;
    #pragma unroll
    for (int i = 0; i < 8; i++) {
        uint32_t g = (uint32_t)tid * 8u + i;
        uint32_t off = (g >> 4) * 256u + (g & 15u) * 16u;
        asm volatile("cp.async.cg.shared.global [%0], [%1], 16;" :: "r"(sdst + SWZ(off)), "l"(s + off) : "memory");
    }
}
// B tile: 16KB (64 col-rows x 256B), 4 x 16B per thread
__device__ __forceinline__ void pf_b(uint32_t sdst, const __nv_bfloat16* src, int tid) {
    const char* s = (const char*)src;
    #pragma unroll
    for (int i = 0; i < 4; i++) {
        uint32_t g = (uint32_t)tid * 4u + i;
        uint32_t off = (g >> 4) * 256u + (g & 15u) * 16u;
        asm volatile("cp.async.cg.shared.global [%0], [%1], 16;" :: "r"(sdst + SWZ(off)), "l"(s + off) : "memory");
    }
}
__device__ __forceinline__ void lse_merge(float& M, float& S, float m2, float s2) {
    if (m2 > M) { S = S * __expf(M - m2) + s2; M = m2; }
    else if (m2 != -INFINITY) S += s2 * __expf(m2 - M);
}

// ============ kernel 1: fp32 -> bf16 row-major ============
__global__ void conv_kernel(const float* __restrict__ ts, const float* __restrict__ nt) {
    int id = blockIdx.x * blockDim.x + threadIdx.x;  // 262144
    int mat = id >> 17;
    int r = id & 131071;
    int row = r >> 4, g = r & 15;
    const float* src = (mat ? nt : ts) + (size_t)row * DDIM + g * 8;
    float4 v0 = *(const float4*)(src);
    float4 v1 = *(const float4*)(src + 4);
    __nv_bfloat162 b0 = __floats2bfloat162_rn(v0.x, v0.y);
    __nv_bfloat162 b1 = __floats2bfloat162_rn(v0.z, v0.w);
    __nv_bfloat162 b2 = __floats2bfloat162_rn(v1.x, v1.y);
    __nv_bfloat162 b3 = __floats2bfloat162_rn(v1.z, v1.w);
    uint4 pk;
    pk.x = *(uint32_t*)&b0; pk.y = *(uint32_t*)&b1;
    pk.z = *(uint32_t*)&b2; pk.w = *(uint32_t*)&b3;
    uint4* dst = (uint4*)((mat ? g_ntb : g_tsb) + (size_t)row * DDIM) + g;
    *dst = pk;
}

// ============ kernel 2: single-pass GEMM + fused row & col LSE ============
// grid 256: rt = bx>>2 (0..63, 128 rows), js = bx&3 (2048-col slice)
// CTA iterates 32 tiles of 128x64; warp tile 32x32 (mwarp=wid>>1, nwarp=wid&1)
#define SMEM_A 0
#define SMEM_B0 32768
#define SMEM_B1 49152
#define SMEM_RED 65536
#define DYN_SMEM (65536 + 2048 + 1024)

__global__ void __launch_bounds__(256, 2) cont_mma() {
    extern __shared__ __align__(16) char smraw[];
    const uint32_t sb = (smem_u32(smraw) + 1023u) & ~1023u;
    const uint32_t sA = sb + SMEM_A, sB0 = sb + SMEM_B0, sB1 = sb + SMEM_B1;
    float2* red = (float2*)(smraw + ((sb - smem_u32(smraw)) + SMEM_RED));

    const int tid = threadIdx.x, lid = tid & 31, wid = tid >> 5;
    const int mwarp = wid >> 1, nwarp = wid & 1;
    const int bx = blockIdx.x;
    const int rt = bx >> 2, js = bx & 3;
    const int r0 = rt * 128;
    const __nv_bfloat16* Ag = g_tsb + (size_t)r0 * DDIM;
    const __nv_bfloat16* Bg = g_ntb + (size_t)js * 2048 * DDIM;

    // prologue: G0 = {A, B0}, G1 = {B1}
    pf_a(sA, Ag, tid);
    pf_b(sB0, Bg, tid);
    asm volatile("cp.async.commit_group;" ::: "memory");
    pf_b(sB1, Bg + 64 * DDIM, tid);
    asm volatile("cp.async.commit_group;" ::: "memory");

    const uint32_t X = (uint32_t)(lid & 7) << 4;
    const uint32_t cA = ((lid >> 4) & 1) * 16u;
    const uint32_t cB = ((lid >> 3) & 1) * 16u;
    uint32_t rowA[2], rowB[2];
    #pragma unroll
    for (int mt = 0; mt < 2; mt++)
        rowA[mt] = (uint32_t)(mwarp * 32 + mt * 16 + (lid & 15)) * 256u;
    #pragma unroll
    for (int np = 0; np < 2; np++)
        rowB[np] = (uint32_t)(nwarp * 32 + np * 16 + (lid & 7) + ((lid >> 4) & 1) * 8) * 256u;

    float m4[4], s4[4];
    #pragma unroll
    for (int i = 0; i < 4; i++) { m4[i] = -INFINITY; s4[i] = 0.0f; }

    for (int jt = 0; jt < 32; jt++) {
        const uint32_t sBuf = (jt & 1) ? sB1 : sB0;
        if (jt < 31) asm volatile("cp.async.wait_group 1;" ::: "memory");
        else         asm volatile("cp.async.wait_group 0;" ::: "memory");
        __syncthreads();   // B ready; also: prior tile's red merge done

        float acc[2][4][4];
        #pragma unroll
        for (int mt = 0; mt < 2; mt++)
            #pragma unroll
            for (int nt = 0; nt < 4; nt++)
                #pragma unroll
                for (int q = 0; q < 4; q++) acc[mt][nt][q] = 0.0f;

        #pragma unroll
        for (int kt = 0; kt < 8; kt++) {
            const uint32_t kb = (uint32_t)kt * 32u;
            uint32_t bfr[4][2];
            #pragma unroll
            for (int np = 0; np < 2; np++) {
                uint32_t t[4];
                ldsm_x4(t, sBuf + rowB[np] + ((kb + cB) ^ X));
                bfr[np * 2][0] = t[0]; bfr[np * 2][1] = t[1];
                bfr[np * 2 + 1][0] = t[2]; bfr[np * 2 + 1][1] = t[3];
            }
            #pragma unroll
            for (int mt = 0; mt < 2; mt++) {
                uint32_t afr[4];
                ldsm_x4(afr, sA + rowA[mt] + ((kb + cA) ^ X));
                #pragma unroll
                for (int nt = 0; nt < 4; nt++)
                    mma_bf16(acc[mt][nt], afr, bfr[nt]);
            }
        }

        const int cb = js * 2048 + jt * 64;
        const bool masked = ((unsigned)(cb - r0) < 128u);
        float cmx[8], csum[8];

        if (!masked) {
            // ---- row online LSE ----
            #pragma unroll
            for (int mt = 0; mt < 2; mt++)
            #pragma unroll
            for (int h = 0; h < 2; h++) {
                const int rs = mt * 2 + h;
                float amax = acc[mt][0][h * 2];
                #pragma unroll
                for (int nt = 0; nt < 4; nt++)
                    #pragma unroll
                    for (int c = 0; c < 2; c++)
                        amax = fmaxf(amax, acc[mt][nt][h * 2 + c]);
                const float vm = amax * INVT;
                if (vm > m4[rs]) { s4[rs] *= __expf(m4[rs] - vm); m4[rs] = vm; }
                const float thr = (m4[rs] - 25.0f) * (1.0f / INVT);
                #pragma unroll
                for (int nt = 0; nt < 4; nt++)
                    #pragma unroll
                    for (int c = 0; c < 2; c++) {
                        const float a = acc[mt][nt][h * 2 + c];
                        if (a > thr) s4[rs] += __expf(fmaf(a, INVT, -m4[rs]));
                    }
            }
            // ---- col tile LSE: max pass ----
            #pragma unroll
            for (int nt = 0; nt < 4; nt++)
            #pragma unroll
            for (int c = 0; c < 2; c++) {
                const int ix = nt * 2 + c;
                float v = acc[0][nt][c];
                v = fmaxf(v, acc[0][nt][2 + c]);
                v = fmaxf(v, acc[1][nt][c]);
                v = fmaxf(v, acc[1][nt][2 + c]);
                cmx[ix] = v;
            }
        } else {
            // ---- masked tile (rare): block-diag mask + diag capture ----
            #pragma unroll
            for (int mt = 0; mt < 2; mt++)
            #pragma unroll
            for (int h = 0; h < 2; h++) {
                const int rs = mt * 2 + h;
                const int gi = r0 + mwarp * 32 + mt * 16 + (lid >> 2) + h * 8;
                #pragma unroll
                for (int nt = 0; nt < 4; nt++)
                    #pragma unroll
                    for (int c = 0; c < 2; c++) {
                        const int gj = cb + nwarp * 32 + nt * 8 + (lid & 3) * 2 + c;
                        const float v = acc[mt][nt][h * 2 + c] * INVT;
                        const bool sameblk = (((gi ^ gj) >> 4) == 0);
                        const bool isdiag = (gi == gj);
                        if (isdiag) g_diag[gi] = v;
                        if (!sameblk || isdiag) {
                            if (v > m4[rs]) { s4[rs] = s4[rs] * __expf(m4[rs] - v) + 1.0f; m4[rs] = v; }
                            else if (v > m4[rs] - 25.0f) s4[rs] += __expf(v - m4[rs]);
                        }
                    }
            }
            #pragma unroll
            for (int nt = 0; nt < 4; nt++)
            #pragma unroll
            for (int c = 0; c < 2; c++) {
                const int ix = nt * 2 + c;
                const int gj = cb + nwarp * 32 + nt * 8 + (lid & 3) * 2 + c;
                float v = -INFINITY;
                #pragma unroll
                for (int mt = 0; mt < 2; mt++)
                    #pragma unroll
                    for (int h = 0; h < 2; h++) {
                        const int gi = r0 + mwarp * 32 + mt * 16 + (lid >> 2) + h * 8;
                        const bool keep = (((gi ^ gj) >> 4) != 0) || (gi == gj);
                        if (keep) v = fmaxf(v, acc[mt][nt][h * 2 + c]);
                    }
                cmx[ix] = v;
            }
        }

        // merge col max across the 8 lanes holding this column (lid>>2 varies)
        #pragma unroll
        for (int ix = 0; ix < 8; ix++) {
            #pragma unroll
            for (int d = 4; d <= 16; d <<= 1)
                cmx[ix] = fmaxf(cmx[ix], __shfl_xor_sync(0xFFFFFFFFu, cmx[ix], d));
        }
        // col sum pass (guarded exp)
        if (!masked) {
            #pragma unroll
            for (int nt = 0; nt < 4; nt++)
            #pragma unroll
            for (int c = 0; c < 2; c++) {
                const int ix = nt * 2 + c;
                const float ML = cmx[ix] * INVT;
                const float thr = cmx[ix] - 0.25f;
                float s = 0.0f;
                #pragma unroll
                for (int mt = 0; mt < 2; mt++)
                    #pragma unroll
                    for (int h = 0; h < 2; h++) {
                        const float a = acc[mt][nt][h * 2 + c];
                        if (a > thr) s += __expf(fmaf(a, INVT, -ML));
                    }
                csum[ix] = s;
            }
        } else {
            #pragma unroll
            for (int nt = 0; nt < 4; nt++)
            #pragma unroll
            for (int c = 0; c < 2; c++) {
                const int ix = nt * 2 + c;
                const int gj = cb + nwarp * 32 + nt * 8 + (lid & 3) * 2 + c;
                const float ML = cmx[ix] * INVT;
                const float thr = cmx[ix] - 0.25f;
                float s = 0.0f;
                #pragma unroll
                for (int mt = 0; mt < 2; mt++)
                    #pragma unroll
                    for (int h = 0; h < 2; h++) {
                        const int gi = r0 + mwarp * 32 + mt * 16 + (lid >> 2) + h * 8;
                        const bool keep = (((gi ^ gj) >> 4) != 0) || (gi == gj);
                        const float a = acc[mt][nt][h * 2 + c];
                        if (keep && a > thr) s += __expf(fmaf(a, INVT, -ML));
                    }
                csum[ix] = s;
            }
        }
        #pragma unroll
        for (int ix = 0; ix < 8; ix++) {
            #pragma unroll
            for (int d = 4; d <= 16; d <<= 1)
                csum[ix] += __shfl_xor_sync(0xFFFFFFFFu, csum[ix], d);
        }
        if (lid < 4) {
            #pragma unroll
            for (int nt = 0; nt < 4; nt++)
                #pragma unroll
                for (int c = 0; c < 2; c++)
                    red[(nwarp * 32 + nt * 8 + lid * 2 + c) * 4 + mwarp] =
                        make_float2(cmx[nt * 2 + c] * INVT, csum[nt * 2 + c]);
        }
        __syncthreads();   // red filled; also mainloop done -> safe to refill sBuf
        if (tid < 64) {
            float2 p0 = red[tid * 4 + 0], p1 = red[tid * 4 + 1];
            float2 p2 = red[tid * 4 + 2], p3 = red[tid * 4 + 3];
            float M = p0.x, S = p0.y;
            lse_merge(M, S, p1.x, p1.y);
            lse_merge(M, S, p2.x, p2.y);
            lse_merge(M, S, p3.x, p3.y);
            g_colp[rt][cb + tid] = make_float2(M, S);
        }
        if (jt + 2 < 32) {
            pf_b(sBuf, Bg + (size_t)(jt + 2) * 64 * DDIM, tid);
            asm volatile("cp.async.commit_group;" ::: "memory");
        }
    }

    // row flush: merge the 4 lanes (lid&3) sharing each row
    #pragma unroll
    for (int mt = 0; mt < 2; mt++)
    #pragma unroll
    for (int h = 0; h < 2; h++) {
        const int rs = mt * 2 + h;
        float m = m4[rs], s = s4[rs];
        #pragma unroll
        for (int d = 1; d <= 2; d <<= 1) {
            float om = __shfl_xor_sync(0xFFFFFFFFu, m, d);
            float os = __shfl_xor_sync(0xFFFFFFFFu, s, d);
            lse_merge(m, s, om, os);
        }
        if ((lid & 3) == 0) {
            const int row = r0 + mwarp * 32 + mt * 16 + (lid >> 2) + h * 8;
            g_rowp[row][js * 2 + nwarp] = make_float2(m, s);
        }
    }
}

// ============ kernel 3: per-index terms + block sums ============
__global__ void cont_fin() {
    __shared__ float rs[256];
    const int tid = threadIdx.x;
    const int i = blockIdx.x * 256 + tid;
    float M = -INFINITY, S = 0.0f;
    #pragma unroll
    for (int k = 0; k < 8; k++) {
        float2 p = g_rowp[i][k];
        lse_merge(M, S, p.x, p.y);
    }
    const float lser = M + __logf(S);
    M = -INFINITY; S = 0.0f;
    for (int p = 0; p < 64; p++) {
        float2 q = g_colp[p][i];
        lse_merge(M, S, q.x, q.y);
    }
    const float lsec = M + __logf(S);
    rs[tid] = 0.5f * (lser + lsec) - g_diag[i];
    __syncthreads();
    for (int o = 128; o > 0; o >>= 1) {
        if (tid < o) rs[tid] += rs[tid + o];
        __syncthreads();
    }
    if (tid == 0) g_bsum[blockIdx.x] = rs[0];
}

// ============ kernel 4: final scalar ============
__global__ void cont_fin2(float* out) {
    float v = g_bsum[threadIdx.x];
    #pragma unroll
    for (int d = 16; d > 0; d >>= 1) v += __shfl_xor_sync(0xFFFFFFFFu, v, d);
    if (threadIdx.x == 0) {
        float loss = v / (float)NTOT;
        if (isnan(loss) || isinf(loss)) loss = 0.0f;
        out[0] = loss;
    }
}

extern "C" void kernel_launch(void* const* d_in, const int* in_sizes, int n_in,
                              void* d_out, int out_size) {
    const float* ts = (const float*)d_in[0];
    const float* nt = (const float*)d_in[1];
    (void)in_sizes; (void)n_in; (void)out_size;

    conv_kernel<<<1024, 256>>>(ts, nt);
    cudaFuncSetAttribute(cont_mma, cudaFuncAttributeMaxDynamicSharedMemorySize, DYN_SMEM);
    cont_mma<<<256, 256, DYN_SMEM>>>();
    cont_fin<<<32, 256>>>();
    cont_fin2<<<1, 32>>>((float*)d_out);
}

// round 6
// speedup vs baseline: 7.1629x; 1.1086x over previous
#include <cuda_runtime.h>
#include <cuda_bf16.h>
#include <cstdint>
#include <math.h>

// Shapes fixed: ts/note (512,16,128) fp32 -> N=8192, D=128
#define NTOT 8192
#define DDIM 128
#define INVT 100.0f

// ---------------- device globals (no dynamic alloc allowed) ----------------
__device__ __align__(16) __nv_bfloat16 g_tsb[NTOT * DDIM];
__device__ __align__(16) __nv_bfloat16 g_ntb[NTOT * DDIM];
__device__ float g_diag[NTOT];
__device__ __align__(16) float2 g_rowp[NTOT][8];     // [row][js*2 + nwarp]
__device__ __align__(16) float2 g_colp[64][NTOT];    // [rt][col]
__device__ float g_bsum[32];
__device__ unsigned g_cnt;                            // zero-init; reset by last block

// ---------------- helpers ----------------
__device__ __forceinline__ uint32_t smem_u32(const void* p) {
    uint32_t a;
    asm("{ .reg .u64 t; cvta.to.shared.u64 t, %1; cvt.u32.u64 %0, t; }" : "=r"(a) : "l"(p));
    return a;
}
// swizzle for 256B rows: XOR 16B-unit index bits[6:4] with row&7 (bits[10:8])
#define SWZ(off) ((off) ^ (((off) >> 4) & 0x70u))

__device__ __forceinline__ void ldsm_x4(uint32_t* r, uint32_t addr) {
    asm volatile("ldmatrix.sync.aligned.m8n8.x4.shared.b16 {%0,%1,%2,%3}, [%4];"
        : "=r"(r[0]), "=r"(r[1]), "=r"(r[2]), "=r"(r[3]) : "r"(addr));
}
__device__ __forceinline__ void mma_bf16(float* c, const uint32_t* a, const uint32_t* b) {
    asm volatile("mma.sync.aligned.m16n8k16.row.col.f32.bf16.bf16.f32 "
        "{%0,%1,%2,%3}, {%4,%5,%6,%7}, {%8,%9}, {%0,%1,%2,%3};"
        : "+f"(c[0]), "+f"(c[1]), "+f"(c[2]), "+f"(c[3])
        : "r"(a[0]), "r"(a[1]), "r"(a[2]), "r"(a[3]), "r"(b[0]), "r"(b[1]));
}
// A tile: 32KB (128 rows x 256B), 8 x 16B per thread
__device__ __forceinline__ void pf_a(uint32_t sdst, const __nv_bfloat16* src, int tid) {
    const char* s = (const char*)src;
    #pragma unroll
    for (int i = 0; i < 8; i++) {
        uint32_t g = (uint32_t)tid * 8u + i;
        uint32_t off = (g >> 4) * 256u + (g & 15u) * 16u;
        asm volatile("cp.async.cg.shared.global [%0], [%1], 16;" :: "r"(sdst + SWZ(off)), "l"(s + off) : "memory");
    }
}
// B tile: 16KB (64 col-rows x 256B), 4 x 16B per thread
__device__ __forceinline__ void pf_b(uint32_t sdst, const __nv_bfloat16* src, int tid) {
    const char* s = (const char*)src;
    #pragma unroll
    for (int i = 0; i < 4; i++) {
        uint32_t g = (uint32_t)tid * 4u + i;
        uint32_t off = (g >> 4) * 256u + (g & 15u) * 16u;
        asm volatile("cp.async.cg.shared.global [%0], [%1], 16;" :: "r"(sdst + SWZ(off)), "l"(s + off) : "memory");
    }
}
__device__ __forceinline__ void lse_merge(float& M, float& S, float m2, float s2) {
    if (m2 > M) { S = S * __expf(M - m2) + s2; M = m2; }
    else if (m2 != -INFINITY) S += s2 * __expf(m2 - M);
}

// ============ kernel 1: fp32 -> bf16 row-major ============
__global__ void conv_kernel(const float* __restrict__ ts, const float* __restrict__ nt) {
    int id = blockIdx.x * blockDim.x + threadIdx.x;  // 262144
    int mat = id >> 17;
    int r = id & 131071;
    int row = r >> 4, g = r & 15;
    const float* src = (mat ? nt : ts) + (size_t)row * DDIM + g * 8;
    float4 v0 = *(const float4*)(src);
    float4 v1 = *(const float4*)(src + 4);
    __nv_bfloat162 b0 = __floats2bfloat162_rn(v0.x, v0.y);
    __nv_bfloat162 b1 = __floats2bfloat162_rn(v0.z, v0.w);
    __nv_bfloat162 b2 = __floats2bfloat162_rn(v1.x, v1.y);
    __nv_bfloat162 b3 = __floats2bfloat162_rn(v1.z, v1.w);
    uint4 pk;
    pk.x = *(uint32_t*)&b0; pk.y = *(uint32_t*)&b1;
    pk.z = *(uint32_t*)&b2; pk.w = *(uint32_t*)&b3;
    uint4* dst = (uint4*)((mat ? g_ntb : g_tsb) + (size_t)row * DDIM) + g;
    *dst = pk;
}

// ============ kernel 2: single-pass GEMM + fused row & col LSE ============
// grid 256: rt = bx>>2 (0..63, 128 rows), js = bx&3 (2048-col slice)
// CTA iterates 32 tiles of 128x64; warp tile 32x32 (mwarp=wid>>1, nwarp=wid&1)
// A fragments for k in [0,64) live in registers for the whole kernel.
#define SMEM_A 0
#define SMEM_B0 32768
#define SMEM_B1 49152
#define SMEM_RED 65536
#define DYN_SMEM (65536 + 2048 + 1024)

__global__ void __launch_bounds__(256, 2) cont_mma() {
    extern __shared__ __align__(16) char smraw[];
    const uint32_t sb = (smem_u32(smraw) + 1023u) & ~1023u;
    const uint32_t sA = sb + SMEM_A, sB0 = sb + SMEM_B0, sB1 = sb + SMEM_B1;
    float2* red = (float2*)(smraw + ((sb - smem_u32(smraw)) + SMEM_RED));

    const int tid = threadIdx.x, lid = tid & 31, wid = tid >> 5;
    const int mwarp = wid >> 1, nwarp = wid & 1;
    const int bx = blockIdx.x;
    const int rt = bx >> 2, js = bx & 3;
    const int r0 = rt * 128;
    const __nv_bfloat16* Ag = g_tsb + (size_t)r0 * DDIM;
    const __nv_bfloat16* Bg = g_ntb + (size_t)js * 2048 * DDIM;

    // prologue: G0 = {A, B0}, G1 = {B1}
    pf_a(sA, Ag, tid);
    pf_b(sB0, Bg, tid);
    asm volatile("cp.async.commit_group;" ::: "memory");
    pf_b(sB1, Bg + 64 * DDIM, tid);
    asm volatile("cp.async.commit_group;" ::: "memory");

    const uint32_t X = (uint32_t)(lid & 7) << 4;
    const uint32_t cA = ((lid >> 4) & 1) * 16u;
    const uint32_t cB = ((lid >> 3) & 1) * 16u;
    uint32_t rowA[2], rowB[2];
    #pragma unroll
    for (int mt = 0; mt < 2; mt++)
        rowA[mt] = (uint32_t)(mwarp * 32 + mt * 16 + (lid & 15)) * 256u;
    #pragma unroll
    for (int np = 0; np < 2; np++)
        rowB[np] = (uint32_t)(nwarp * 32 + np * 16 + (lid & 7) + ((lid >> 4) & 1) * 8) * 256u;

    float m4[4], s4[4];
    #pragma unroll
    for (int i = 0; i < 4; i++) { m4[i] = -INFINITY; s4[i] = 0.0f; }

    uint32_t areg[2][4][4];   // resident A fragments, k in [0,64)

    for (int jt = 0; jt < 32; jt++) {
        const uint32_t sBuf = (jt & 1) ? sB1 : sB0;
        if (jt < 31) asm volatile("cp.async.wait_group 1;" ::: "memory");
        else         asm volatile("cp.async.wait_group 0;" ::: "memory");
        __syncthreads();   // B ready; also: prior tile's red merge done

        if (jt == 0) {
            // one-time preload of the low-K A fragments into registers
            #pragma unroll
            for (int mt = 0; mt < 2; mt++)
                #pragma unroll
                for (int kt = 0; kt < 4; kt++)
                    ldsm_x4(areg[mt][kt], sA + rowA[mt] + (((uint32_t)kt * 32u + cA) ^ X));
        }

        float acc[2][4][4];
        #pragma unroll
        for (int mt = 0; mt < 2; mt++)
            #pragma unroll
            for (int nt = 0; nt < 4; nt++)
                #pragma unroll
                for (int q = 0; q < 4; q++) acc[mt][nt][q] = 0.0f;

        // k in [0,64): A from registers
        #pragma unroll
        for (int kt = 0; kt < 4; kt++) {
            const uint32_t kb = (uint32_t)kt * 32u;
            uint32_t bfr[4][2];
            #pragma unroll
            for (int np = 0; np < 2; np++) {
                uint32_t t[4];
                ldsm_x4(t, sBuf + rowB[np] + ((kb + cB) ^ X));
                bfr[np * 2][0] = t[0]; bfr[np * 2][1] = t[1];
                bfr[np * 2 + 1][0] = t[2]; bfr[np * 2 + 1][1] = t[3];
            }
            #pragma unroll
            for (int mt = 0; mt < 2; mt++)
                #pragma unroll
                for (int nt = 0; nt < 4; nt++)
                    mma_bf16(acc[mt][nt], areg[mt][kt], bfr[nt]);
        }
        // k in [64,128): A from smem
        #pragma unroll
        for (int kt = 4; kt < 8; kt++) {
            const uint32_t kb = (uint32_t)kt * 32u;
            uint32_t bfr[4][2];
            #pragma unroll
            for (int np = 0; np < 2; np++) {
                uint32_t t[4];
                ldsm_x4(t, sBuf + rowB[np] + ((kb + cB) ^ X));
                bfr[np * 2][0] = t[0]; bfr[np * 2][1] = t[1];
                bfr[np * 2 + 1][0] = t[2]; bfr[np * 2 + 1][1] = t[3];
            }
            #pragma unroll
            for (int mt = 0; mt < 2; mt++) {
                uint32_t afr[4];
                ldsm_x4(afr, sA + rowA[mt] + ((kb + cA) ^ X));
                #pragma unroll
                for (int nt = 0; nt < 4; nt++)
                    mma_bf16(acc[mt][nt], afr, bfr[nt]);
            }
        }

        const int cb = js * 2048 + jt * 64;
        const bool masked = ((unsigned)(cb - r0) < 128u);
        float cmx[8], csum[8];

        if (!masked) {
            // ---- row online LSE ----
            #pragma unroll
            for (int mt = 0; mt < 2; mt++)
            #pragma unroll
            for (int h = 0; h < 2; h++) {
                const int rs = mt * 2 + h;
                float amax = acc[mt][0][h * 2];
                #pragma unroll
                for (int nt = 0; nt < 4; nt++)
                    #pragma unroll
                    for (int c = 0; c < 2; c++)
                        amax = fmaxf(amax, acc[mt][nt][h * 2 + c]);
                const float vm = amax * INVT;
                if (vm > m4[rs]) { s4[rs] *= __expf(m4[rs] - vm); m4[rs] = vm; }
                const float thr = (m4[rs] - 25.0f) * (1.0f / INVT);
                #pragma unroll
                for (int nt = 0; nt < 4; nt++)
                    #pragma unroll
                    for (int c = 0; c < 2; c++) {
                        const float a = acc[mt][nt][h * 2 + c];
                        if (a > thr) s4[rs] += __expf(fmaf(a, INVT, -m4[rs]));
                    }
            }
            // ---- col tile max pass ----
            #pragma unroll
            for (int nt = 0; nt < 4; nt++)
            #pragma unroll
            for (int c = 0; c < 2; c++) {
                const int ix = nt * 2 + c;
                float v = acc[0][nt][c];
                v = fmaxf(v, acc[0][nt][2 + c]);
                v = fmaxf(v, acc[1][nt][c]);
                v = fmaxf(v, acc[1][nt][2 + c]);
                cmx[ix] = v;
            }
        } else {
            // ---- masked tile (rare): block-diag mask + diag capture ----
            #pragma unroll
            for (int mt = 0; mt < 2; mt++)
            #pragma unroll
            for (int h = 0; h < 2; h++) {
                const int rs = mt * 2 + h;
                const int gi = r0 + mwarp * 32 + mt * 16 + (lid >> 2) + h * 8;
                #pragma unroll
                for (int nt = 0; nt < 4; nt++)
                    #pragma unroll
                    for (int c = 0; c < 2; c++) {
                        const int gj = cb + nwarp * 32 + nt * 8 + (lid & 3) * 2 + c;
                        const float v = acc[mt][nt][h * 2 + c] * INVT;
                        const bool sameblk = (((gi ^ gj) >> 4) == 0);
                        const bool isdiag = (gi == gj);
                        if (isdiag) g_diag[gi] = v;
                        if (!sameblk || isdiag) {
                            if (v > m4[rs]) { s4[rs] = s4[rs] * __expf(m4[rs] - v) + 1.0f; m4[rs] = v; }
                            else if (v > m4[rs] - 25.0f) s4[rs] += __expf(v - m4[rs]);
                        }
                    }
            }
            #pragma unroll
            for (int nt = 0; nt < 4; nt++)
            #pragma unroll
            for (int c = 0; c < 2; c++) {
                const int ix = nt * 2 + c;
                const int gj = cb + nwarp * 32 + nt * 8 + (lid & 3) * 2 + c;
                float v = -INFINITY;
                #pragma unroll
                for (int mt = 0; mt < 2; mt++)
                    #pragma unroll
                    for (int h = 0; h < 2; h++) {
                        const int gi = r0 + mwarp * 32 + mt * 16 + (lid >> 2) + h * 8;
                        const bool keep = (((gi ^ gj) >> 4) != 0) || (gi == gj);
                        if (keep) v = fmaxf(v, acc[mt][nt][h * 2 + c]);
                    }
                cmx[ix] = v;
            }
        }

        // merge col max across the 8 lanes holding this column (lid>>2 varies)
        #pragma unroll
        for (int ix = 0; ix < 8; ix++) {
            #pragma unroll
            for (int d = 4; d <= 16; d <<= 1)
                cmx[ix] = fmaxf(cmx[ix], __shfl_xor_sync(0xFFFFFFFFu, cmx[ix], d));
        }
        // col sum pass (guarded exp)
        if (!masked) {
            #pragma unroll
            for (int nt = 0; nt < 4; nt++)
            #pragma unroll
            for (int c = 0; c < 2; c++) {
                const int ix = nt * 2 + c;
                const float ML = cmx[ix] * INVT;
                const float thr = cmx[ix] - 0.25f;
                float s = 0.0f;
                #pragma unroll
                for (int mt = 0; mt < 2; mt++)
                    #pragma unroll
                    for (int h = 0; h < 2; h++) {
                        const float a = acc[mt][nt][h * 2 + c];
                        if (a > thr) s += __expf(fmaf(a, INVT, -ML));
                    }
                csum[ix] = s;
            }
        } else {
            #pragma unroll
            for (int nt = 0; nt < 4; nt++)
            #pragma unroll
            for (int c = 0; c < 2; c++) {
                const int ix = nt * 2 + c;
                const int gj = cb + nwarp * 32 + nt * 8 + (lid & 3) * 2 + c;
                const float ML = cmx[ix] * INVT;
                const float thr = cmx[ix] - 0.25f;
                float s = 0.0f;
                #pragma unroll
                for (int mt = 0; mt < 2; mt++)
                    #pragma unroll
                    for (int h = 0; h < 2; h++) {
                        const int gi = r0 + mwarp * 32 + mt * 16 + (lid >> 2) + h * 8;
                        const bool keep = (((gi ^ gj) >> 4) != 0) || (gi == gj);
                        const float a = acc[mt][nt][h * 2 + c];
                        if (keep && a > thr) s += __expf(fmaf(a, INVT, -ML));
                    }
                csum[ix] = s;
            }
        }
        #pragma unroll
        for (int ix = 0; ix < 8; ix++) {
            #pragma unroll
            for (int d = 4; d <= 16; d <<= 1)
                csum[ix] += __shfl_xor_sync(0xFFFFFFFFu, csum[ix], d);
        }
        if (lid < 4) {
            #pragma unroll
            for (int nt = 0; nt < 4; nt++)
                #pragma unroll
                for (int c = 0; c < 2; c++)
                    red[(nwarp * 32 + nt * 8 + lid * 2 + c) * 4 + mwarp] =
                        make_float2(cmx[nt * 2 + c] * INVT, csum[nt * 2 + c]);
        }
        __syncthreads();   // red filled; also mainloop done -> safe to refill sBuf
        if (tid < 64) {
            float2 p0 = red[tid * 4 + 0], p1 = red[tid * 4 + 1];
            float2 p2 = red[tid * 4 + 2], p3 = red[tid * 4 + 3];
            float M = p0.x, S = p0.y;
            lse_merge(M, S, p1.x, p1.y);
            lse_merge(M, S, p2.x, p2.y);
            lse_merge(M, S, p3.x, p3.y);
            g_colp[rt][cb + tid] = make_float2(M, S);
        }
        if (jt + 2 < 32) {
            pf_b(sBuf, Bg + (size_t)(jt + 2) * 64 * DDIM, tid);
            asm volatile("cp.async.commit_group;" ::: "memory");
        }
    }

    // row flush: merge the 4 lanes (lid&3) sharing each row
    #pragma unroll
    for (int mt = 0; mt < 2; mt++)
    #pragma unroll
    for (int h = 0; h < 2; h++) {
        const int rs = mt * 2 + h;
        float m = m4[rs], s = s4[rs];
        #pragma unroll
        for (int d = 1; d <= 2; d <<= 1) {
            float om = __shfl_xor_sync(0xFFFFFFFFu, m, d);
            float os = __shfl_xor_sync(0xFFFFFFFFu, s, d);
            lse_merge(m, s, om, os);
        }
        if ((lid & 3) == 0) {
            const int row = r0 + mwarp * 32 + mt * 16 + (lid >> 2) + h * 8;
            g_rowp[row][js * 2 + nwarp] = make_float2(m, s);
        }
    }
}

// ============ kernel 3: per-index terms + full reduction (last-block) ============
__global__ void cont_fin(float* out) {
    __shared__ float rs[256];
    __shared__ bool last;
    const int tid = threadIdx.x;
    const int i = blockIdx.x * 256 + tid;

    // row LSE: 8 partials, two-pass (max then guarded sum)
    float2 rp[8];
    float M = -INFINITY;
    #pragma unroll
    for (int k = 0; k < 8; k++) { rp[k] = g_rowp[i][k]; M = fmaxf(M, rp[k].x); }
    float S = 0.0f;
    #pragma unroll
    for (int k = 0; k < 8; k++)
        if (rp[k].x > M - 25.0f) S += rp[k].y * __expf(rp[k].x - M);
    const float lser = M + __logf(S);

    // col LSE: 64 partials, two-pass over L2-hot gmem
    float Mc = -INFINITY;
    #pragma unroll 8
    for (int p = 0; p < 64; p++) Mc = fmaxf(Mc, g_colp[p][i].x);
    float Sc = 0.0f;
    #pragma unroll 8
    for (int p = 0; p < 64; p++) {
        float2 q = g_colp[p][i];
        if (q.x > Mc - 25.0f) Sc += q.y * __expf(q.x - Mc);
    }
    const float lsec = Mc + __logf(Sc);

    rs[tid] = 0.5f * (lser + lsec) - g_diag[i];
    __syncthreads();
    for (int o = 128; o > 0; o >>= 1) {
        if (tid < o) rs[tid] += rs[tid + o];
        __syncthreads();
    }
    if (tid == 0) {
        g_bsum[blockIdx.x] = rs[0];
        __threadfence();
        last = (atomicAdd(&g_cnt, 1u) == gridDim.x - 1);
    }
    __syncthreads();
    if (last && tid < 32) {
        __threadfence();
        float v = g_bsum[tid];
        #pragma unroll
        for (int d = 16; d > 0; d >>= 1) v += __shfl_xor_sync(0xFFFFFFFFu, v, d);
        if (tid == 0) {
            float loss = v / (float)NTOT;
            if (isnan(loss) || isinf(loss)) loss = 0.0f;
            out[0] = loss;
            g_cnt = 0;   // reset for next (graph-replayed) launch
        }
    }
}

extern "C" void kernel_launch(void* const* d_in, const int* in_sizes, int n_in,
                              void* d_out, int out_size) {
    const float* ts = (const float*)d_in[0];
    const float* nt = (const float*)d_in[1];
    (void)in_sizes; (void)n_in; (void)out_size;

    conv_kernel<<<1024, 256>>>(ts, nt);
    cudaFuncSetAttribute(cont_mma, cudaFuncAttributeMaxDynamicSharedMemorySize, DYN_SMEM);
    cont_mma<<<256, 256, DYN_SMEM>>>();
    cont_fin<<<32, 256>>>((float*)d_out);
}